// round 11
// baseline (speedup 1.0000x reference)
#include <cuda_runtime.h>
#include <math.h>

#define B_    2
#define L_    4096
#define K_    32
#define HALF_ 128
#define NPAIR 28
#define DPAD  36
#define EPSF  1e-6f
#define TWOPI 6.28318530717958647692f
#define BL_   (B_*L_)
#define GRID_ 608

typedef unsigned long long ull;
typedef long long ll;

__device__ float g_wsym[NPAIR*HALF_];   // 2pi*(W[mn]+W[nm])
__device__ float g_wv[3*HALF_];         // 2pi*W_vec
__device__ float g_bias[HALF_];         // 2pi*sqrt(EPS)*sum_diag W
__device__ float g_fr[BL_*16];          // per res: e1 e2 e3 t (float4 each), masked

__constant__ int c_pm[NPAIR] = {0,0,0,0,0,0,0,1,1,1,1,1,1,2,2,2,2,2,3,3,3,3,4,4,4,5,5,6};
__constant__ int c_pn[NPAIR] = {1,2,3,4,5,6,7,2,3,4,5,6,7,3,4,5,6,7,4,5,6,7,5,6,7,6,7,7};

static __device__ __forceinline__ ull pack2(float lo, float hi){
    ull r; asm("mov.b64 %0, {%1,%2};" : "=l"(r) : "f"(lo), "f"(hi)); return r;
}
static __device__ __forceinline__ void unpack2(ull v, float& lo, float& hi){
    asm("mov.b64 {%0,%1}, %2;" : "=f"(lo), "=f"(hi) : "l"(v));
}
static __device__ __forceinline__ ull fma2(ull a, ull b, ull c){
    ull d; asm("fma.rn.f32x2 %0, %1, %2, %3;" : "=l"(d) : "l"(a), "l"(b), "l"(c)); return d;
}
static __device__ __forceinline__ ull mul2(ull a, ull b){
    ull d; asm("mul.rn.f32x2 %0, %1, %2;" : "=l"(d) : "l"(a), "l"(b)); return d;
}
static __device__ __forceinline__ ull dup2(float x){ return pack2(x, x); }

static __device__ __forceinline__ unsigned sa(const void* p){
    return (unsigned)__cvta_generic_to_shared(p);
}
static __device__ __forceinline__ void cp16(unsigned s, const void* g){
    asm volatile("cp.async.ca.shared.global [%0], [%1], 16;" :: "r"(s), "l"(g));
}
static __device__ __forceinline__ void cp8(unsigned s, const void* g){
    asm volatile("cp.async.ca.shared.global [%0], [%1], 8;" :: "r"(s), "l"(g));
}
static __device__ __forceinline__ void cp4(unsigned s, const void* g){
    asm volatile("cp.async.ca.shared.global [%0], [%1], 4;" :: "r"(s), "l"(g));
}

// ---------------------------------------------------------------------------
// Prep: block 0 = W preparation; blocks 1..32 = frames (masked R rows + t).
// ---------------------------------------------------------------------------
__global__ void prep_kernel(const float* __restrict__ X, const void* __restrict__ Cv,
                            const float* __restrict__ Wvec, const float* __restrict__ Wdist){
    if (blockIdx.x == 0){
        int e = threadIdx.x;
        if (e >= 128) return;
        #pragma unroll
        for (int d = 0; d < 3; d++) g_wv[d*HALF_ + e] = TWOPI * Wvec[d*HALF_ + e];
        float b = 0.f;
        #pragma unroll
        for (int m = 0; m < 8; m++) b += Wdist[(m*8+m)*HALF_ + e];
        g_bias[e] = TWOPI * sqrtf(EPSF) * b;
        for (int p = 0; p < NPAIR; p++){
            int m = c_pm[p], n = c_pn[p];
            g_wsym[p*HALF_ + e] = TWOPI * (Wdist[(m*8+n)*HALF_ + e] + Wdist[(n*8+m)*HALF_ + e]);
        }
        return;
    }
    int r = (blockIdx.x - 1)*256 + threadIdx.x;   // 32*256 = 8192
    int4 vc = ((const int4*)Cv)[threadIdx.x & 31];
    int is64C = (__reduce_or_sync(0xffffffffu, vc.y | vc.w) == 0);
    ll cv = is64C ? ((const ll*)Cv)[r] : (ll)((const int*)Cv)[r];
    float mask = (cv > 0) ? 1.f : 0.f;

    const float* x = X + (size_t)r * 12;
    float Nx=x[0], Ny=x[1], Nz=x[2];
    float Ax=x[3], Ay=x[4], Az=x[5];
    float Cx=x[6], Cy=x[7], Cz=x[8];

    float v1x=Nx-Ax, v1y=Ny-Ay, v1z=Nz-Az;
    float n1 = sqrtf(v1x*v1x + v1y*v1y + v1z*v1z) + EPSF;
    float e1x=v1x/n1, e1y=v1y/n1, e1z=v1z/n1;

    float u2x=Cx-Ax, u2y=Cy-Ay, u2z=Cz-Az;
    float n2 = sqrtf(u2x*u2x + u2y*u2y + u2z*u2z) + EPSF;
    u2x/=n2; u2y/=n2; u2z/=n2;

    float dt = u2x*e1x + u2y*e1y + u2z*e1z;
    float w2x = u2x - dt*e1x, w2y = u2y - dt*e1y, w2z = u2z - dt*e1z;
    float n3 = sqrtf(w2x*w2x + w2y*w2y + w2z*w2z) + EPSF;
    float e2x=w2x/n3, e2y=w2y/n3, e2z=w2z/n3;

    float e3x = e1y*e2z - e1z*e2y;
    float e3y = e1z*e2x - e1x*e2z;
    float e3z = e1x*e2y - e1y*e2x;

    float4* g4 = (float4*)g_fr + (size_t)r*4;
    g4[0] = make_float4(mask*e1x, mask*e1y, mask*e1z, 0.f);
    g4[1] = make_float4(mask*e2x, mask*e2y, mask*e2z, 0.f);
    g4[2] = make_float4(mask*e3x, mask*e3y, mask*e3z, 0.f);
    g4[3] = make_float4(mask*Ax,  mask*Ay,  mask*Az,  0.f);
}

// ---------------------------------------------------------------------------
// Persistent main kernel: R9 structure; hd loop uses EDGE-PACKED accumulators
// (d operands adjacent from LDS, only W needs dup) + post-loop reg transpose.
// ---------------------------------------------------------------------------
__global__ __launch_bounds__(256, 4)
void edge_kernel(const float* __restrict__ X, const void* __restrict__ eidxv,
                 float* __restrict__ out){
    __shared__ __align__(16) float s_wsym[NPAIR*HALF_];  // 14336 B
    __shared__ __align__(16) float s_wv[3*HALF_];        // 1536 B
    __shared__ __align__(16) float s_bias[HALF_];        // 512 B
    __shared__ __align__(16) float s_xj[2][K_*12];       // 3072 B
    __shared__ __align__(16) float s_tj[2][K_*4];        // 1024 B
    __shared__ __align__(16) float s_fri[2][16];         // 128 B
    __shared__ __align__(16) float s_xi[2][12];          // 96 B
    __shared__ __align__(16) ll    s_jb[2][K_];          // 512 B
    __shared__ __align__(16) float s_d[NPAIR*DPAD];      // 4032 B: s_d[p*36 + e]
    __shared__ __align__(16) float s_t[K_*4];            // 512 B

    int tid  = threadIdx.x;
    int w    = tid >> 5, lane = tid & 31;

    int4 ve = ((const int4*)eidxv)[lane];
    int is64 = (__reduce_or_sync(0xffffffffu, ve.y | ve.w) == 0);

    // W staging once per block
    {
        const float4* src = (const float4*)g_wsym;
        float4* dst = (float4*)s_wsym;
        #pragma unroll
        for (int i = tid; i < NPAIR*HALF_/4; i += 256) dst[i] = src[i];
    }
    if (tid < 96)                ((float4*)s_wv)[tid]      = ((const float4*)g_wv)[tid];
    if (tid >= 96 && tid < 128)  ((float4*)s_bias)[tid-96] = ((const float4*)g_bias)[tid-96];

    int kk_x = 0, part_x = 0;
    if (tid < 96){ kk_x = tid/3; part_x = tid - kk_x*3; }

    // --- prologue: synchronous staging of residue r0 + jbuf for r0+GRID ---
    int r = blockIdx.x;
    {
        int bb = r & ~(L_-1);
        if (tid < 96){
            ll j = is64 ? ((const ll*)eidxv)[r*K_ + kk_x]
                        : (ll)((const int*)eidxv)[r*K_ + kk_x];
            ((float4*)&s_xj[0][kk_x*12])[part_x] = ((const float4*)X)[(bb+(int)j)*3 + part_x];
        } else if (tid < 128){
            int k = tid - 96;
            ll j = is64 ? ((const ll*)eidxv)[r*K_ + k]
                        : (ll)((const int*)eidxv)[r*K_ + k];
            ((float4*)&s_tj[0][k*4])[0] = ((const float4*)g_fr)[(size_t)(bb+(int)j)*4 + 3];
        } else if (tid < 132){
            ((float4*)s_fri[0])[tid-128] = ((const float4*)g_fr)[(size_t)r*4 + (tid-128)];
        } else if (tid < 135){
            ((float4*)s_xi[0])[tid-132] = ((const float4*)X)[r*3 + (tid-132)];
        } else if (tid >= 136 && tid < 168 && r + GRID_ < BL_){
            int k = tid - 136;
            s_jb[0][k] = is64 ? ((const ll*)eidxv)[(r+GRID_)*K_ + k]
                              : (ll)((const int*)eidxv)[(r+GRID_)*K_ + k];
        }
    }
    __syncthreads();

    int b = 0;
    while (true){
        int rn = r + GRID_;
        bool hn = rn < BL_;

        // --- zero-register prefetch for rn via cp.async ---
        if (hn){
            int bb = rn & ~(L_-1);
            if (tid < 96){
                ll j = is64 ? s_jb[b][kk_x] : (ll)(*(const int*)&s_jb[b][kk_x]);
                cp16(sa(&s_xj[b^1][kk_x*12 + part_x*4]),
                     (const char*)X + ((size_t)(bb+(int)j)*12 + part_x*4)*4);
            } else if (tid < 128){
                int k = tid - 96;
                ll j = is64 ? s_jb[b][k] : (ll)(*(const int*)&s_jb[b][k]);
                cp16(sa(&s_tj[b^1][k*4]),
                     (const char*)g_fr + ((size_t)(bb+(int)j)*16 + 12)*4);
            } else if (tid < 132){
                cp16(sa(&s_fri[b^1][(tid-128)*4]),
                     (const char*)g_fr + ((size_t)rn*16 + (tid-128)*4)*4);
            } else if (tid < 135){
                cp16(sa(&s_xi[b^1][(tid-132)*4]),
                     (const char*)X + ((size_t)rn*12 + (tid-132)*4)*4);
            } else if (tid >= 136 && tid < 168 && rn + GRID_ < BL_){
                int k = tid - 136;
                if (is64) cp8(sa(&s_jb[b^1][k]),
                              (const char*)eidxv + ((size_t)(rn+GRID_)*K_ + k)*8);
                else      cp4(sa(&s_jb[b^1][k]),
                              (const char*)eidxv + ((size_t)(rn+GRID_)*K_ + k)*4);
            }
            asm volatile("cp.async.commit_group;" ::: "memory");
        }

        // --- distance + t_ji phase: warp w -> edges w*4..w*4+3 ---
        if (lane < NPAIR){
            int m = c_pm[lane], n = c_pn[lane];
            bool mI = (m < 4), nI = (n < 4);
            float mx=0.f,my=0.f,mz=0.f, nx=0.f,ny=0.f,nz=0.f;
            if (mI){ mx=s_xi[b][m*3]; my=s_xi[b][m*3+1]; mz=s_xi[b][m*3+2]; }
            if (nI){ nx=s_xi[b][n*3]; ny=s_xi[b][n*3+1]; nz=s_xi[b][n*3+2]; }
            #pragma unroll
            for (int e = 0; e < 4; e++){
                int k = w*4 + e;
                const float* xj = &s_xj[b][k*12];
                float ax = mI ? mx : xj[(m-4)*3+0];
                float ay = mI ? my : xj[(m-4)*3+1];
                float az = mI ? mz : xj[(m-4)*3+2];
                float bx = nI ? nx : xj[(n-4)*3+0];
                float by = nI ? ny : xj[(n-4)*3+1];
                float bz = nI ? nz : xj[(n-4)*3+2];
                float dx=ax-bx, dy=ay-by, dz=az-bz;
                float dd = fmaf(dx,dx, fmaf(dy,dy, fmaf(dz,dz, EPSF)));
                s_d[lane*DPAD + k] = __fsqrt_rn(dd);   // [pair][edge] layout
            }
        } else {
            int k = w*4 + (lane - NPAIR);
            float4 f0 = ((const float4*)s_fri[b])[0];
            float4 f1 = ((const float4*)s_fri[b])[1];
            float4 f2 = ((const float4*)s_fri[b])[2];
            float4 f3 = ((const float4*)s_fri[b])[3];
            float4 tj = ((const float4*)&s_tj[b][k*4])[0];
            float dx = tj.x - f3.x, dy = tj.y - f3.y, dz = tj.z - f3.z;
            float t0 = fmaf(f0.z,dz, fmaf(f0.y,dy, f0.x*dx));
            float t1 = fmaf(f1.z,dz, fmaf(f1.y,dy, f1.x*dx));
            float t2 = fmaf(f2.z,dz, fmaf(f2.y,dy, f2.x*dx));
            ((float4*)&s_t[k*4])[0] = make_float4(t0, t1, t2, 0.f);
        }
        __syncthreads();

        // --- compute phase: warp (cg,eg): 64 cols x 8 edges, EDGE-PACKED hd ---
        {
            int cg = w >> 2;
            int eg = w & 3;
            int col = cg*64 + lane*2;     // cols c0=col, c1=col+1
            int eb  = eg * 8;

            // acc0[j] = {hd[eb+2j][c0], hd[eb+2j+1][c0]}, acc1[j] = same for c1
            ull acc0[4], acc1[4];
            {
                float2 bq = *(const float2*)&s_bias[col];
                ull b0 = dup2(bq.x), b1 = dup2(bq.y);
                #pragma unroll
                for (int j = 0; j < 4; j++){ acc0[j]=b0; acc1[j]=b1; }
            }
            #pragma unroll 2
            for (int p = 0; p < NPAIR; p++){
                float2 wq = *(const float2*)&s_wsym[p*HALF_ + col];  // {W[p][c0],W[p][c1]}
                ull W0 = dup2(wq.x), W1 = dup2(wq.y);
                float4 dq0 = *(const float4*)&s_d[p*DPAD + eb];      // d[eb..eb+3] broadcast
                float4 dq1 = *(const float4*)&s_d[p*DPAD + eb + 4];  // d[eb+4..eb+7]
                ull d01 = pack2(dq0.x, dq0.y);   // adjacent -> free packing
                ull d23 = pack2(dq0.z, dq0.w);
                ull d45 = pack2(dq1.x, dq1.y);
                ull d67 = pack2(dq1.z, dq1.w);
                acc0[0] = fma2(d01, W0, acc0[0]);  acc1[0] = fma2(d01, W1, acc1[0]);
                acc0[1] = fma2(d23, W0, acc0[1]);  acc1[1] = fma2(d23, W1, acc1[1]);
                acc0[2] = fma2(d45, W0, acc0[2]);  acc1[2] = fma2(d45, W1, acc1[2]);
                acc0[3] = fma2(d67, W0, acc0[3]);  acc1[3] = fma2(d67, W1, acc1[3]);
            }

            // transpose to col-packed: hd[e] = {hd[e][c0], hd[e][c1]}
            ull hd[8];
            #pragma unroll
            for (int j = 0; j < 4; j++){
                float a0,a1,c0f,c1f;
                unpack2(acc0[j], a0, a1);     // hd[2j][c0], hd[2j+1][c0]
                unpack2(acc1[j], c0f, c1f);   // hd[2j][c1], hd[2j+1][c1]
                hd[2*j]   = pack2(a0, c0f);
                hd[2*j+1] = pack2(a1, c1f);
            }

            float2 wv0 = *(const float2*)&s_wv[0*HALF_ + col];
            float2 wv1 = *(const float2*)&s_wv[1*HALF_ + col];
            float2 wv2 = *(const float2*)&s_wv[2*HALF_ + col];
            ull v0 = pack2(wv0.x, wv0.y);
            ull v1 = pack2(wv1.x, wv1.y);
            ull v2 = pack2(wv2.x, wv2.y);

            #pragma unroll
            for (int e = 0; e < 8; e++){
                int k = eb + e;
                float4 tq = *(const float4*)&s_t[k*4];   // broadcast
                ull hv = fma2(dup2(tq.z), v2, fma2(dup2(tq.y), v1, mul2(dup2(tq.x), v0)));

                float a0,a1,b0,b1;
                unpack2(hv, a0, a1);
                unpack2(hd[e], b0, b1);
                float sa0,ca0,sa1,ca1,sb0,cb0,sb1,cb1;
                __sincosf(a0,&sa0,&ca0); __sincosf(a1,&sa1,&ca1);
                __sincosf(b0,&sb0,&cb0); __sincosf(b1,&sb1,&cb1);
                size_t obase = ((size_t)(r*K_ + k))*256 + col;
                __stcs((float2*)&out[obase],       make_float2(ca0+cb0, ca1+cb1));
                __stcs((float2*)&out[obase + 128], make_float2(sa0+sb0, sa1+sb1));
            }
        }

        asm volatile("cp.async.wait_group 0;" ::: "memory");
        __syncthreads();
        if (!hn) break;
        r = rn; b ^= 1;
    }
}

// ---------------------------------------------------------------------------
extern "C" void kernel_launch(void* const* d_in, const int* in_sizes, int n_in,
                              void* d_out, int out_size){
    const float* X     = (const float*)d_in[0];
    const void*  eidx  = d_in[1];
    const void*  C     = d_in[2];
    const float* Wvec  = (const float*)d_in[3];
    const float* Wdist = (const float*)d_in[4];
    (void)in_sizes; (void)n_in; (void)out_size;

    prep_kernel<<<33, 256>>>(X, C, Wvec, Wdist);
    edge_kernel<<<GRID_, 256>>>(X, eidx, (float*)d_out);
}

// round 13
// speedup vs baseline: 1.3732x; 1.3732x over previous
#include <cuda_runtime.h>
#include <math.h>

#define B_    2
#define L_    4096
#define K_    32
#define HALF_ 128
#define NPAIR 28
#define EPSF  1e-6f
#define TWOPI 6.28318530717958647692f
#define BL_   (B_*L_)
#define GRID_ 608

typedef unsigned long long ull;
typedef long long ll;

// Pair-pair interleaved W: for q=0..13, colpair cp=0..63:
//   g_wq[q*256 + cp*4 + 0] = W[2q  ][2cp]
//   g_wq[q*256 + cp*4 + 1] = W[2q+1][2cp]
//   g_wq[q*256 + cp*4 + 2] = W[2q  ][2cp+1]
//   g_wq[q*256 + cp*4 + 3] = W[2q+1][2cp+1]
__device__ float g_wq[14*256];
__device__ float g_wv[3*HALF_];         // 2pi*W_vec
__device__ float g_bias[HALF_];         // 2pi*sqrt(EPS)*sum_diag W
__device__ float g_fr[BL_*16];          // per res: e1 e2 e3 t (float4 each), masked

__constant__ int c_pm[NPAIR] = {0,0,0,0,0,0,0,1,1,1,1,1,1,2,2,2,2,2,3,3,3,3,4,4,4,5,5,6};
__constant__ int c_pn[NPAIR] = {1,2,3,4,5,6,7,2,3,4,5,6,7,3,4,5,6,7,4,5,6,7,5,6,7,6,7,7};

static __device__ __forceinline__ ull pack2(float lo, float hi){
    ull r; asm("mov.b64 %0, {%1,%2};" : "=l"(r) : "f"(lo), "f"(hi)); return r;
}
static __device__ __forceinline__ void unpack2(ull v, float& lo, float& hi){
    asm("mov.b64 {%0,%1}, %2;" : "=f"(lo), "=f"(hi) : "l"(v));
}
static __device__ __forceinline__ ull fma2(ull a, ull b, ull c){
    ull d; asm("fma.rn.f32x2 %0, %1, %2, %3;" : "=l"(d) : "l"(a), "l"(b), "l"(c)); return d;
}
static __device__ __forceinline__ ull mul2(ull a, ull b){
    ull d; asm("mul.rn.f32x2 %0, %1, %2;" : "=l"(d) : "l"(a), "l"(b)); return d;
}
static __device__ __forceinline__ ull dup2(float x){ return pack2(x, x); }

static __device__ __forceinline__ unsigned sa(const void* p){
    return (unsigned)__cvta_generic_to_shared(p);
}
static __device__ __forceinline__ void cp16(unsigned s, const void* g){
    asm volatile("cp.async.ca.shared.global [%0], [%1], 16;" :: "r"(s), "l"(g));
}
static __device__ __forceinline__ void cp8(unsigned s, const void* g){
    asm volatile("cp.async.ca.shared.global [%0], [%1], 8;" :: "r"(s), "l"(g));
}
static __device__ __forceinline__ void cp4(unsigned s, const void* g){
    asm volatile("cp.async.ca.shared.global [%0], [%1], 4;" :: "r"(s), "l"(g));
}

// ---------------------------------------------------------------------------
// Prep: block 0 = W preparation; blocks 1..32 = frames (masked R rows + t).
// ---------------------------------------------------------------------------
__global__ void prep_kernel(const float* __restrict__ X, const void* __restrict__ Cv,
                            const float* __restrict__ Wvec, const float* __restrict__ Wdist){
    if (blockIdx.x == 0){
        int e = threadIdx.x;
        if (e >= 128) return;
        #pragma unroll
        for (int d = 0; d < 3; d++) g_wv[d*HALF_ + e] = TWOPI * Wvec[d*HALF_ + e];
        float b = 0.f;
        #pragma unroll
        for (int m = 0; m < 8; m++) b += Wdist[(m*8+m)*HALF_ + e];
        g_bias[e] = TWOPI * sqrtf(EPSF) * b;
        for (int p = 0; p < NPAIR; p++){
            int m = c_pm[p], n = c_pn[p];
            float v = TWOPI * (Wdist[(m*8+n)*HALF_ + e] + Wdist[(n*8+m)*HALF_ + e]);
            g_wq[(p>>1)*256 + (e>>1)*4 + (e&1)*2 + (p&1)] = v;
        }
        return;
    }
    int r = (blockIdx.x - 1)*256 + threadIdx.x;   // 32*256 = 8192
    int4 vc = ((const int4*)Cv)[threadIdx.x & 31];
    int is64C = (__reduce_or_sync(0xffffffffu, vc.y | vc.w) == 0);
    ll cv = is64C ? ((const ll*)Cv)[r] : (ll)((const int*)Cv)[r];
    float mask = (cv > 0) ? 1.f : 0.f;

    const float* x = X + (size_t)r * 12;
    float Nx=x[0], Ny=x[1], Nz=x[2];
    float Ax=x[3], Ay=x[4], Az=x[5];
    float Cx=x[6], Cy=x[7], Cz=x[8];

    float v1x=Nx-Ax, v1y=Ny-Ay, v1z=Nz-Az;
    float n1 = sqrtf(v1x*v1x + v1y*v1y + v1z*v1z) + EPSF;
    float e1x=v1x/n1, e1y=v1y/n1, e1z=v1z/n1;

    float u2x=Cx-Ax, u2y=Cy-Ay, u2z=Cz-Az;
    float n2 = sqrtf(u2x*u2x + u2y*u2y + u2z*u2z) + EPSF;
    u2x/=n2; u2y/=n2; u2z/=n2;

    float dt = u2x*e1x + u2y*e1y + u2z*e1z;
    float w2x = u2x - dt*e1x, w2y = u2y - dt*e1y, w2z = u2z - dt*e1z;
    float n3 = sqrtf(w2x*w2x + w2y*w2y + w2z*w2z) + EPSF;
    float e2x=w2x/n3, e2y=w2y/n3, e2z=w2z/n3;

    float e3x = e1y*e2z - e1z*e2y;
    float e3y = e1z*e2x - e1x*e2z;
    float e3z = e1x*e2y - e1y*e2x;

    float4* g4 = (float4*)g_fr + (size_t)r*4;
    g4[0] = make_float4(mask*e1x, mask*e1y, mask*e1z, 0.f);
    g4[1] = make_float4(mask*e2x, mask*e2y, mask*e2z, 0.f);
    g4[2] = make_float4(mask*e3x, mask*e3y, mask*e3z, 0.f);
    g4[3] = make_float4(mask*Ax,  mask*Ay,  mask*Az,  0.f);
}

// ---------------------------------------------------------------------------
// Persistent main kernel (R9 staging/prefetch verbatim). hd loop uses f32x2
// as a dot-product accumulator over pair-pairs: both operands adjacent-packed
// (zero dup MOVs). 2 tiles of 4 edges per warp; horizontal lo+hi at the end.
// ---------------------------------------------------------------------------
__global__ __launch_bounds__(256, 4)
void edge_kernel(const float* __restrict__ X, const void* __restrict__ eidxv,
                 float* __restrict__ out){
    __shared__ __align__(16) float s_wq[14*256];         // 14336 B
    __shared__ __align__(16) float s_wv[3*HALF_];        // 1536 B
    __shared__ __align__(16) float s_bias[HALF_];        // 512 B
    __shared__ __align__(16) float s_xj[2][K_*12];       // 3072 B
    __shared__ __align__(16) float s_tj[2][K_*4];        // 1024 B
    __shared__ __align__(16) float s_fri[2][16];         // 128 B
    __shared__ __align__(16) float s_xi[2][12];          // 96 B
    __shared__ __align__(16) ll    s_jb[2][K_];          // 512 B
    __shared__ __align__(16) float s_d[K_*NPAIR];        // 3584 B: s_d[edge*28+pair]
    __shared__ __align__(16) float s_t[K_*4];            // 512 B

    int tid  = threadIdx.x;
    int w    = tid >> 5, lane = tid & 31;

    int4 ve = ((const int4*)eidxv)[lane];
    int is64 = (__reduce_or_sync(0xffffffffu, ve.y | ve.w) == 0);

    // W staging once per block
    {
        const float4* src = (const float4*)g_wq;
        float4* dst = (float4*)s_wq;
        #pragma unroll
        for (int i = tid; i < 14*256/4; i += 256) dst[i] = src[i];
    }
    if (tid < 96)                ((float4*)s_wv)[tid]      = ((const float4*)g_wv)[tid];
    if (tid >= 96 && tid < 128)  ((float4*)s_bias)[tid-96] = ((const float4*)g_bias)[tid-96];

    int kk_x = 0, part_x = 0;
    if (tid < 96){ kk_x = tid/3; part_x = tid - kk_x*3; }

    // --- prologue: synchronous staging of residue r0 + jbuf for r0+GRID ---
    int r = blockIdx.x;
    {
        int bb = r & ~(L_-1);
        if (tid < 96){
            ll j = is64 ? ((const ll*)eidxv)[r*K_ + kk_x]
                        : (ll)((const int*)eidxv)[r*K_ + kk_x];
            ((float4*)&s_xj[0][kk_x*12])[part_x] = ((const float4*)X)[(bb+(int)j)*3 + part_x];
        } else if (tid < 128){
            int k = tid - 96;
            ll j = is64 ? ((const ll*)eidxv)[r*K_ + k]
                        : (ll)((const int*)eidxv)[r*K_ + k];
            ((float4*)&s_tj[0][k*4])[0] = ((const float4*)g_fr)[(size_t)(bb+(int)j)*4 + 3];
        } else if (tid < 132){
            ((float4*)s_fri[0])[tid-128] = ((const float4*)g_fr)[(size_t)r*4 + (tid-128)];
        } else if (tid < 135){
            ((float4*)s_xi[0])[tid-132] = ((const float4*)X)[r*3 + (tid-132)];
        } else if (tid >= 136 && tid < 168 && r + GRID_ < BL_){
            int k = tid - 136;
            s_jb[0][k] = is64 ? ((const ll*)eidxv)[(r+GRID_)*K_ + k]
                              : (ll)((const int*)eidxv)[(r+GRID_)*K_ + k];
        }
    }
    __syncthreads();

    int b = 0;
    while (true){
        int rn = r + GRID_;
        bool hn = rn < BL_;

        // --- zero-register prefetch for rn via cp.async ---
        if (hn){
            int bb = rn & ~(L_-1);
            if (tid < 96){
                ll j = is64 ? s_jb[b][kk_x] : (ll)(*(const int*)&s_jb[b][kk_x]);
                cp16(sa(&s_xj[b^1][kk_x*12 + part_x*4]),
                     (const char*)X + ((size_t)(bb+(int)j)*12 + part_x*4)*4);
            } else if (tid < 128){
                int k = tid - 96;
                ll j = is64 ? s_jb[b][k] : (ll)(*(const int*)&s_jb[b][k]);
                cp16(sa(&s_tj[b^1][k*4]),
                     (const char*)g_fr + ((size_t)(bb+(int)j)*16 + 12)*4);
            } else if (tid < 132){
                cp16(sa(&s_fri[b^1][(tid-128)*4]),
                     (const char*)g_fr + ((size_t)rn*16 + (tid-128)*4)*4);
            } else if (tid < 135){
                cp16(sa(&s_xi[b^1][(tid-132)*4]),
                     (const char*)X + ((size_t)rn*12 + (tid-132)*4)*4);
            } else if (tid >= 136 && tid < 168 && rn + GRID_ < BL_){
                int k = tid - 136;
                if (is64) cp8(sa(&s_jb[b^1][k]),
                              (const char*)eidxv + ((size_t)(rn+GRID_)*K_ + k)*8);
                else      cp4(sa(&s_jb[b^1][k]),
                              (const char*)eidxv + ((size_t)(rn+GRID_)*K_ + k)*4);
            }
            asm volatile("cp.async.commit_group;" ::: "memory");
        }

        // --- distance + t_ji phase: warp w -> edges w*4..w*4+3 ---
        if (lane < NPAIR){
            int m = c_pm[lane], n = c_pn[lane];
            bool mI = (m < 4), nI = (n < 4);
            float mx=0.f,my=0.f,mz=0.f, nx=0.f,ny=0.f,nz=0.f;
            if (mI){ mx=s_xi[b][m*3]; my=s_xi[b][m*3+1]; mz=s_xi[b][m*3+2]; }
            if (nI){ nx=s_xi[b][n*3]; ny=s_xi[b][n*3+1]; nz=s_xi[b][n*3+2]; }
            #pragma unroll
            for (int e = 0; e < 4; e++){
                int k = w*4 + e;
                const float* xj = &s_xj[b][k*12];
                float ax = mI ? mx : xj[(m-4)*3+0];
                float ay = mI ? my : xj[(m-4)*3+1];
                float az = mI ? mz : xj[(m-4)*3+2];
                float bx = nI ? nx : xj[(n-4)*3+0];
                float by = nI ? ny : xj[(n-4)*3+1];
                float bz = nI ? nz : xj[(n-4)*3+2];
                float dx=ax-bx, dy=ay-by, dz=az-bz;
                float dd = fmaf(dx,dx, fmaf(dy,dy, fmaf(dz,dz, EPSF)));
                s_d[k*NPAIR + lane] = __fsqrt_rn(dd);
            }
        } else {
            int k = w*4 + (lane - NPAIR);
            float4 f0 = ((const float4*)s_fri[b])[0];
            float4 f1 = ((const float4*)s_fri[b])[1];
            float4 f2 = ((const float4*)s_fri[b])[2];
            float4 f3 = ((const float4*)s_fri[b])[3];
            float4 tj = ((const float4*)&s_tj[b][k*4])[0];
            float dx = tj.x - f3.x, dy = tj.y - f3.y, dz = tj.z - f3.z;
            float t0 = fmaf(f0.z,dz, fmaf(f0.y,dy, f0.x*dx));
            float t1 = fmaf(f1.z,dz, fmaf(f1.y,dy, f1.x*dx));
            float t2 = fmaf(f2.z,dz, fmaf(f2.y,dy, f2.x*dx));
            ((float4*)&s_t[k*4])[0] = make_float4(t0, t1, t2, 0.f);
        }
        __syncthreads();

        // --- compute phase: warp (cg,eg): 64 cols (2/lane) x 8 edges in 2 tiles ---
        {
            int cg = w >> 2;
            int eg = w & 3;
            int colp = cg*32 + lane;       // colpair index 0..63
            int col  = colp*2;

            float2 bq = *(const float2*)&s_bias[col];
            float2 wv0 = *(const float2*)&s_wv[0*HALF_ + col];
            float2 wv1 = *(const float2*)&s_wv[1*HALF_ + col];
            float2 wv2 = *(const float2*)&s_wv[2*HALF_ + col];
            ull v0 = pack2(wv0.x, wv0.y);
            ull v1 = pack2(wv1.x, wv1.y);
            ull v2 = pack2(wv2.x, wv2.y);

            #pragma unroll
            for (int tile = 0; tile < 2; tile++){
                int eb = eg*8 + tile*4;

                // acc[e][c]: f32x2 dot-product accumulator {even-pair sum, odd-pair sum}
                ull acc00 = pack2(bq.x, 0.f), acc01 = pack2(bq.y, 0.f);
                ull acc10 = pack2(bq.x, 0.f), acc11 = pack2(bq.y, 0.f);
                ull acc20 = pack2(bq.x, 0.f), acc21 = pack2(bq.y, 0.f);
                ull acc30 = pack2(bq.x, 0.f), acc31 = pack2(bq.y, 0.f);

                #pragma unroll 1
                for (int qq = 0; qq < 7; qq++){
                    float4 wqa = *(const float4*)&s_wq[(2*qq+0)*256 + colp*4];
                    float4 wqb = *(const float4*)&s_wq[(2*qq+1)*256 + colp*4];
                    ull Wa0 = pack2(wqa.x, wqa.y);   // {W[4qq  ][c0], W[4qq+1][c0]}
                    ull Wa1 = pack2(wqa.z, wqa.w);   // {W[4qq  ][c1], W[4qq+1][c1]}
                    ull Wb0 = pack2(wqb.x, wqb.y);   // {W[4qq+2][c0], W[4qq+3][c0]}
                    ull Wb1 = pack2(wqb.z, wqb.w);
                    float4 d0 = *(const float4*)&s_d[(eb+0)*NPAIR + qq*4];  // broadcast
                    float4 d1 = *(const float4*)&s_d[(eb+1)*NPAIR + qq*4];
                    float4 d2 = *(const float4*)&s_d[(eb+2)*NPAIR + qq*4];
                    float4 d3 = *(const float4*)&s_d[(eb+3)*NPAIR + qq*4];
                    ull d0a = pack2(d0.x,d0.y), d0b = pack2(d0.z,d0.w);
                    ull d1a = pack2(d1.x,d1.y), d1b = pack2(d1.z,d1.w);
                    ull d2a = pack2(d2.x,d2.y), d2b = pack2(d2.z,d2.w);
                    ull d3a = pack2(d3.x,d3.y), d3b = pack2(d3.z,d3.w);
                    acc00 = fma2(d0a, Wa0, acc00);  acc01 = fma2(d0a, Wa1, acc01);
                    acc00 = fma2(d0b, Wb0, acc00);  acc01 = fma2(d0b, Wb1, acc01);
                    acc10 = fma2(d1a, Wa0, acc10);  acc11 = fma2(d1a, Wa1, acc11);
                    acc10 = fma2(d1b, Wb0, acc10);  acc11 = fma2(d1b, Wb1, acc11);
                    acc20 = fma2(d2a, Wa0, acc20);  acc21 = fma2(d2a, Wa1, acc21);
                    acc20 = fma2(d2b, Wb0, acc20);  acc21 = fma2(d2b, Wb1, acc21);
                    acc30 = fma2(d3a, Wa0, acc30);  acc31 = fma2(d3a, Wa1, acc31);
                    acc30 = fma2(d3b, Wb0, acc30);  acc31 = fma2(d3b, Wb1, acc31);
                }

                ull accA[4] = {acc00, acc10, acc20, acc30};
                ull accB[4] = {acc01, acc11, acc21, acc31};
                #pragma unroll
                for (int e = 0; e < 4; e++){
                    int k = eb + e;
                    float lo0, hi0, lo1, hi1;
                    unpack2(accA[e], lo0, hi0);
                    unpack2(accB[e], lo1, hi1);
                    float b0 = lo0 + hi0, b1 = lo1 + hi1;   // hd[k][c0], hd[k][c1]

                    float4 tq = *(const float4*)&s_t[k*4];  // broadcast
                    ull hv = fma2(dup2(tq.z), v2, fma2(dup2(tq.y), v1, mul2(dup2(tq.x), v0)));
                    float a0, a1;
                    unpack2(hv, a0, a1);

                    float sa0,ca0,sa1,ca1,sb0,cb0,sb1,cb1;
                    __sincosf(a0,&sa0,&ca0); __sincosf(a1,&sa1,&ca1);
                    __sincosf(b0,&sb0,&cb0); __sincosf(b1,&sb1,&cb1);
                    size_t obase = ((size_t)(r*K_ + k))*256 + col;
                    __stcs((float2*)&out[obase],       make_float2(ca0+cb0, ca1+cb1));
                    __stcs((float2*)&out[obase + 128], make_float2(sa0+sb0, sa1+sb1));
                }
            }
        }

        asm volatile("cp.async.wait_group 0;" ::: "memory");
        __syncthreads();
        if (!hn) break;
        r = rn; b ^= 1;
    }
}

// ---------------------------------------------------------------------------
extern "C" void kernel_launch(void* const* d_in, const int* in_sizes, int n_in,
                              void* d_out, int out_size){
    const float* X     = (const float*)d_in[0];
    const void*  eidx  = d_in[1];
    const void*  C     = d_in[2];
    const float* Wvec  = (const float*)d_in[3];
    const float* Wdist = (const float*)d_in[4];
    (void)in_sizes; (void)n_in; (void)out_size;

    prep_kernel<<<33, 256>>>(X, C, Wvec, Wdist);
    edge_kernel<<<GRID_, 256>>>(X, eidx, (float*)d_out);
}

// round 14
// speedup vs baseline: 1.6046x; 1.1685x over previous
#include <cuda_runtime.h>
#include <math.h>

#define B_    2
#define L_    4096
#define K_    32
#define HALF_ 128
#define NPAIR 28
#define EPSF  1e-6f
#define TWOPI 6.28318530717958647692f
#define BL_   (B_*L_)
#define GRID_ 608

typedef unsigned long long ull;
typedef long long ll;

__device__ float g_wsym[NPAIR*HALF_];   // 2pi*(W[mn]+W[nm])
__device__ float g_wv[3*HALF_];         // 2pi*W_vec
__device__ float g_bias[HALF_];         // 2pi*sqrt(EPS)*sum_diag W
__device__ float g_fr[BL_*16];          // per res: e1 e2 e3 t (float4 each), masked

__constant__ int c_pm[NPAIR] = {0,0,0,0,0,0,0,1,1,1,1,1,1,2,2,2,2,2,3,3,3,3,4,4,4,5,5,6};
__constant__ int c_pn[NPAIR] = {1,2,3,4,5,6,7,2,3,4,5,6,7,3,4,5,6,7,4,5,6,7,5,6,7,6,7,7};

static __device__ __forceinline__ ull pack2(float lo, float hi){
    ull r; asm("mov.b64 %0, {%1,%2};" : "=l"(r) : "f"(lo), "f"(hi)); return r;
}
static __device__ __forceinline__ void unpack2(ull v, float& lo, float& hi){
    asm("mov.b64 {%0,%1}, %2;" : "=f"(lo), "=f"(hi) : "l"(v));
}
static __device__ __forceinline__ ull fma2(ull a, ull b, ull c){
    ull d; asm("fma.rn.f32x2 %0, %1, %2, %3;" : "=l"(d) : "l"(a), "l"(b), "l"(c)); return d;
}
static __device__ __forceinline__ ull mul2(ull a, ull b){
    ull d; asm("mul.rn.f32x2 %0, %1, %2;" : "=l"(d) : "l"(a), "l"(b)); return d;
}
static __device__ __forceinline__ ull dup2(float x){ return pack2(x, x); }

static __device__ __forceinline__ unsigned sa(const void* p){
    return (unsigned)__cvta_generic_to_shared(p);
}
static __device__ __forceinline__ void cp16(unsigned s, const void* g){
    asm volatile("cp.async.ca.shared.global [%0], [%1], 16;" :: "r"(s), "l"(g));
}
static __device__ __forceinline__ void cp8(unsigned s, const void* g){
    asm volatile("cp.async.ca.shared.global [%0], [%1], 8;" :: "r"(s), "l"(g));
}
static __device__ __forceinline__ void cp4(unsigned s, const void* g){
    asm volatile("cp.async.ca.shared.global [%0], [%1], 4;" :: "r"(s), "l"(g));
}

// ---------------------------------------------------------------------------
// Prep: block 0 = W preparation; blocks 1..32 = frames (masked R rows + t).
// ---------------------------------------------------------------------------
__global__ void prep_kernel(const float* __restrict__ X, const void* __restrict__ Cv,
                            const float* __restrict__ Wvec, const float* __restrict__ Wdist){
    if (blockIdx.x == 0){
        int e = threadIdx.x;
        if (e >= 128) return;
        #pragma unroll
        for (int d = 0; d < 3; d++) g_wv[d*HALF_ + e] = TWOPI * Wvec[d*HALF_ + e];
        float b = 0.f;
        #pragma unroll
        for (int m = 0; m < 8; m++) b += Wdist[(m*8+m)*HALF_ + e];
        g_bias[e] = TWOPI * sqrtf(EPSF) * b;
        for (int p = 0; p < NPAIR; p++){
            int m = c_pm[p], n = c_pn[p];
            g_wsym[p*HALF_ + e] = TWOPI * (Wdist[(m*8+n)*HALF_ + e] + Wdist[(n*8+m)*HALF_ + e]);
        }
        return;
    }
    int r = (blockIdx.x - 1)*256 + threadIdx.x;   // 32*256 = 8192
    int4 vc = ((const int4*)Cv)[threadIdx.x & 31];
    int is64C = (__reduce_or_sync(0xffffffffu, vc.y | vc.w) == 0);
    ll cv = is64C ? ((const ll*)Cv)[r] : (ll)((const int*)Cv)[r];
    float mask = (cv > 0) ? 1.f : 0.f;

    const float* x = X + (size_t)r * 12;
    float Nx=x[0], Ny=x[1], Nz=x[2];
    float Ax=x[3], Ay=x[4], Az=x[5];
    float Cx=x[6], Cy=x[7], Cz=x[8];

    float v1x=Nx-Ax, v1y=Ny-Ay, v1z=Nz-Az;
    float n1 = sqrtf(v1x*v1x + v1y*v1y + v1z*v1z) + EPSF;
    float e1x=v1x/n1, e1y=v1y/n1, e1z=v1z/n1;

    float u2x=Cx-Ax, u2y=Cy-Ay, u2z=Cz-Az;
    float n2 = sqrtf(u2x*u2x + u2y*u2y + u2z*u2z) + EPSF;
    u2x/=n2; u2y/=n2; u2z/=n2;

    float dt = u2x*e1x + u2y*e1y + u2z*e1z;
    float w2x = u2x - dt*e1x, w2y = u2y - dt*e1y, w2z = u2z - dt*e1z;
    float n3 = sqrtf(w2x*w2x + w2y*w2y + w2z*w2z) + EPSF;
    float e2x=w2x/n3, e2y=w2y/n3, e2z=w2z/n3;

    float e3x = e1y*e2z - e1z*e2y;
    float e3y = e1z*e2x - e1x*e2z;
    float e3z = e1x*e2y - e1y*e2x;

    float4* g4 = (float4*)g_fr + (size_t)r*4;
    g4[0] = make_float4(mask*e1x, mask*e1y, mask*e1z, 0.f);
    g4[1] = make_float4(mask*e2x, mask*e2y, mask*e2z, 0.f);
    g4[2] = make_float4(mask*e3x, mask*e3y, mask*e3z, 0.f);
    g4[3] = make_float4(mask*Ax,  mask*Ay,  mask*Az,  0.f);
}

// ---------------------------------------------------------------------------
// Persistent main kernel: R9 hot loop/epilogue verbatim; depth-2 cp.async
// pipeline merges dist(r+G) into the compute(r) span -> 1 barrier/residue.
// ---------------------------------------------------------------------------
__global__ __launch_bounds__(256, 4)
void edge_kernel(const float* __restrict__ X, const void* __restrict__ eidxv,
                 float* __restrict__ out){
    __shared__ __align__(16) float s_wsym[NPAIR*HALF_];  // 14336 B
    __shared__ __align__(16) float s_wv[3*HALF_];        // 1536 B
    __shared__ __align__(16) float s_bias[HALF_];        // 512 B
    __shared__ __align__(16) float s_xj[2][K_*12];       // 3072 B
    __shared__ __align__(16) float s_tj[2][K_*4];        // 1024 B
    __shared__ __align__(16) float s_fri[2][16];         // 128 B
    __shared__ __align__(16) float s_xi[2][12];          // 96 B
    __shared__ __align__(16) ll    s_jb[2][K_];          // 512 B
    __shared__ __align__(16) float s_d[2][K_*NPAIR];     // 7168 B
    __shared__ __align__(16) float s_t[2][K_*4];         // 1024 B

    int tid  = threadIdx.x;
    int w    = tid >> 5, lane = tid & 31;

    int4 ve = ((const int4*)eidxv)[lane];
    int is64 = (__reduce_or_sync(0xffffffffu, ve.y | ve.w) == 0);

    // W staging once per block
    {
        const float4* src = (const float4*)g_wsym;
        float4* dst = (float4*)s_wsym;
        #pragma unroll
        for (int i = tid; i < NPAIR*HALF_/4; i += 256) dst[i] = src[i];
    }
    if (tid < 96)                ((float4*)s_wv)[tid]      = ((const float4*)g_wv)[tid];
    if (tid >= 96 && tid < 128)  ((float4*)s_bias)[tid-96] = ((const float4*)g_bias)[tid-96];

    int kk_x = 0, part_x = 0;
    if (tid < 96){ kk_x = tid/3; part_x = tid - kk_x*3; }

    // synchronous staging of residue rr into slot ss
    auto stage = [&](int rr, int ss){
        int bb = rr & ~(L_-1);
        if (tid < 96){
            ll j = is64 ? ((const ll*)eidxv)[rr*K_ + kk_x]
                        : (ll)((const int*)eidxv)[rr*K_ + kk_x];
            ((float4*)&s_xj[ss][kk_x*12])[part_x] = ((const float4*)X)[(bb+(int)j)*3 + part_x];
        } else if (tid < 128){
            int k = tid - 96;
            ll j = is64 ? ((const ll*)eidxv)[rr*K_ + k]
                        : (ll)((const int*)eidxv)[rr*K_ + k];
            ((float4*)&s_tj[ss][k*4])[0] = ((const float4*)g_fr)[(size_t)(bb+(int)j)*4 + 3];
        } else if (tid < 132){
            ((float4*)s_fri[ss])[tid-128] = ((const float4*)g_fr)[(size_t)rr*4 + (tid-128)];
        } else if (tid < 135){
            ((float4*)s_xi[ss])[tid-132] = ((const float4*)X)[rr*3 + (tid-132)];
        }
    };

    // distance + t_ji for the residue staged in slot ss, writing d-buffer dd
    auto dist = [&](int ss, int dd){
        if (lane < NPAIR){
            int m = c_pm[lane], n = c_pn[lane];
            bool mI = (m < 4), nI = (n < 4);
            float mx=0.f,my=0.f,mz=0.f, nx=0.f,ny=0.f,nz=0.f;
            if (mI){ mx=s_xi[ss][m*3]; my=s_xi[ss][m*3+1]; mz=s_xi[ss][m*3+2]; }
            if (nI){ nx=s_xi[ss][n*3]; ny=s_xi[ss][n*3+1]; nz=s_xi[ss][n*3+2]; }
            #pragma unroll
            for (int e = 0; e < 4; e++){
                int k = w*4 + e;
                const float* xj = &s_xj[ss][k*12];
                float ax = mI ? mx : xj[(m-4)*3+0];
                float ay = mI ? my : xj[(m-4)*3+1];
                float az = mI ? mz : xj[(m-4)*3+2];
                float bx = nI ? nx : xj[(n-4)*3+0];
                float by = nI ? ny : xj[(n-4)*3+1];
                float bz = nI ? nz : xj[(n-4)*3+2];
                float dx=ax-bx, dy=ay-by, dz=az-bz;
                float dd2 = fmaf(dx,dx, fmaf(dy,dy, fmaf(dz,dz, EPSF)));
                s_d[dd][k*NPAIR + lane] = __fsqrt_rn(dd2);
            }
        } else {
            int k = w*4 + (lane - NPAIR);
            float4 f0 = ((const float4*)s_fri[ss])[0];
            float4 f1 = ((const float4*)s_fri[ss])[1];
            float4 f2 = ((const float4*)s_fri[ss])[2];
            float4 f3 = ((const float4*)s_fri[ss])[3];
            float4 tj = ((const float4*)&s_tj[ss][k*4])[0];
            float dx = tj.x - f3.x, dy = tj.y - f3.y, dz = tj.z - f3.z;
            float t0 = fmaf(f0.z,dz, fmaf(f0.y,dy, f0.x*dx));
            float t1 = fmaf(f1.z,dz, fmaf(f1.y,dy, f1.x*dx));
            float t2 = fmaf(f2.z,dz, fmaf(f2.y,dy, f2.x*dx));
            ((float4*)&s_t[dd][k*4])[0] = make_float4(t0, t1, t2, 0.f);
        }
    };

    // --- prologue: stage r0 (slot0) and r0+G (slot1); jb[0] <- idx(r0+2G) ---
    int r0 = blockIdx.x;
    stage(r0, 0);
    if (r0 + GRID_ < BL_) stage(r0 + GRID_, 1);
    if (tid >= 136 && tid < 168 && r0 + 2*GRID_ < BL_){
        int k = tid - 136;
        s_jb[0][k] = is64 ? ((const ll*)eidxv)[(r0+2*GRID_)*K_ + k]
                          : (ll)((const int*)eidxv)[(r0+2*GRID_)*K_ + k];
    }
    __syncthreads();
    dist(0, 0);
    __syncthreads();

    int r = r0, xb = 1, db = 0;
    while (true){
        int rn = r + GRID_;
        int rf = r + 2*GRID_;
        bool hn = rn < BL_;

        // --- prefetch xj(rf) into slot xb^1 (uses jb[xb^1]); jb[xb] <- idx(r+3G) ---
        if (rf < BL_){
            int bb = rf & ~(L_-1);
            if (tid < 96){
                ll j = is64 ? s_jb[xb^1][kk_x] : (ll)(*(const int*)&s_jb[xb^1][kk_x]);
                cp16(sa(&s_xj[xb^1][kk_x*12 + part_x*4]),
                     (const char*)X + ((size_t)(bb+(int)j)*12 + part_x*4)*4);
            } else if (tid < 128){
                int k = tid - 96;
                ll j = is64 ? s_jb[xb^1][k] : (ll)(*(const int*)&s_jb[xb^1][k]);
                cp16(sa(&s_tj[xb^1][k*4]),
                     (const char*)g_fr + ((size_t)(bb+(int)j)*16 + 12)*4);
            } else if (tid < 132){
                cp16(sa(&s_fri[xb^1][(tid-128)*4]),
                     (const char*)g_fr + ((size_t)rf*16 + (tid-128)*4)*4);
            } else if (tid < 135){
                cp16(sa(&s_xi[xb^1][(tid-132)*4]),
                     (const char*)X + ((size_t)rf*12 + (tid-132)*4)*4);
            } else if (tid >= 136 && tid < 168 && r + 3*GRID_ < BL_){
                int k = tid - 136;
                if (is64) cp8(sa(&s_jb[xb][k]),
                              (const char*)eidxv + ((size_t)(r+3*GRID_)*K_ + k)*8);
                else      cp4(sa(&s_jb[xb][k]),
                              (const char*)eidxv + ((size_t)(r+3*GRID_)*K_ + k)*4);
            }
            asm volatile("cp.async.commit_group;" ::: "memory");
        }

        // --- dist(r+G) into s_d[db^1] (hides under other warps' compute) ---
        if (hn) dist(xb, db^1);

        // --- compute(r) from s_d[db] / s_t[db] (R9 hot loop + epilogue) ---
        {
            int cg = w >> 2;
            int eg = w & 3;
            int col = cg*64 + lane*2;
            int eb  = eg * 8;

            ull hd[8];
            {
                float2 bq = *(const float2*)&s_bias[col];
                ull b2 = pack2(bq.x, bq.y);
                #pragma unroll
                for (int e = 0; e < 8; e++) hd[e] = b2;
            }
            #pragma unroll 1
            for (int pp = 0; pp < NPAIR; pp += 4){
                float2 q0 = *(const float2*)&s_wsym[(pp+0)*HALF_ + col];
                float2 q1 = *(const float2*)&s_wsym[(pp+1)*HALF_ + col];
                float2 q2 = *(const float2*)&s_wsym[(pp+2)*HALF_ + col];
                float2 q3 = *(const float2*)&s_wsym[(pp+3)*HALF_ + col];
                ull W0 = pack2(q0.x,q0.y), W1 = pack2(q1.x,q1.y);
                ull W2 = pack2(q2.x,q2.y), W3 = pack2(q3.x,q3.y);
                #pragma unroll
                for (int e = 0; e < 8; e++){
                    float4 dq = *(const float4*)&s_d[db][(eb+e)*NPAIR + pp];  // broadcast
                    hd[e] = fma2(dup2(dq.x), W0, hd[e]);
                    hd[e] = fma2(dup2(dq.y), W1, hd[e]);
                    hd[e] = fma2(dup2(dq.z), W2, hd[e]);
                    hd[e] = fma2(dup2(dq.w), W3, hd[e]);
                }
            }

            float2 wv0 = *(const float2*)&s_wv[0*HALF_ + col];
            float2 wv1 = *(const float2*)&s_wv[1*HALF_ + col];
            float2 wv2 = *(const float2*)&s_wv[2*HALF_ + col];
            ull v0 = pack2(wv0.x, wv0.y);
            ull v1 = pack2(wv1.x, wv1.y);
            ull v2 = pack2(wv2.x, wv2.y);

            #pragma unroll
            for (int e = 0; e < 8; e++){
                int k = eb + e;
                float4 tq = *(const float4*)&s_t[db][k*4];   // broadcast
                ull hv = fma2(dup2(tq.z), v2, fma2(dup2(tq.y), v1, mul2(dup2(tq.x), v0)));

                float a0,a1,b0,b1;
                unpack2(hv, a0, a1);
                unpack2(hd[e], b0, b1);
                float sa0,ca0,sa1,ca1,sb0,cb0,sb1,cb1;
                __sincosf(a0,&sa0,&ca0); __sincosf(a1,&sa1,&ca1);
                __sincosf(b0,&sb0,&cb0); __sincosf(b1,&sb1,&cb1);
                size_t obase = ((size_t)(r*K_ + k))*256 + col;
                __stcs((float2*)&out[obase],       make_float2(ca0+cb0, ca1+cb1));
                __stcs((float2*)&out[obase + 128], make_float2(sa0+sb0, sa1+sb1));
            }
        }

        asm volatile("cp.async.wait_group 0;" ::: "memory");
        __syncthreads();
        if (!hn) break;
        r = rn; xb ^= 1; db ^= 1;
    }
}

// ---------------------------------------------------------------------------
extern "C" void kernel_launch(void* const* d_in, const int* in_sizes, int n_in,
                              void* d_out, int out_size){
    const float* X     = (const float*)d_in[0];
    const void*  eidx  = d_in[1];
    const void*  C     = d_in[2];
    const float* Wvec  = (const float*)d_in[3];
    const float* Wdist = (const float*)d_in[4];
    (void)in_sizes; (void)n_in; (void)out_size;

    prep_kernel<<<33, 256>>>(X, C, Wvec, Wdist);
    edge_kernel<<<GRID_, 256>>>(X, eidx, (float*)d_out);
}

// round 15
// speedup vs baseline: 1.6712x; 1.0416x over previous
#include <cuda_runtime.h>
#include <math.h>

#define B_    2
#define L_    4096
#define K_    32
#define HALF_ 128
#define NPAIR 28
#define EPSF  1e-6f
#define TWOPI 6.28318530717958647692f
#define BL_   (B_*L_)
#define GRID_ 608

typedef unsigned long long ull;
typedef long long ll;

__device__ float g_wsym[NPAIR*HALF_];   // 2pi*(W[mn]+W[nm])
__device__ float g_wv[3*HALF_];         // 2pi*W_vec
__device__ float g_bias[HALF_];         // 2pi*sqrt(EPS)*sum_diag W
__device__ float g_fr[BL_*16];          // per res: e1 e2 e3 t (float4 each), masked

__constant__ int c_pm[NPAIR] = {0,0,0,0,0,0,0,1,1,1,1,1,1,2,2,2,2,2,3,3,3,3,4,4,4,5,5,6};
__constant__ int c_pn[NPAIR] = {1,2,3,4,5,6,7,2,3,4,5,6,7,3,4,5,6,7,4,5,6,7,5,6,7,6,7,7};

static __device__ __forceinline__ ull pack2(float lo, float hi){
    ull r; asm("mov.b64 %0, {%1,%2};" : "=l"(r) : "f"(lo), "f"(hi)); return r;
}
static __device__ __forceinline__ void unpack2(ull v, float& lo, float& hi){
    asm("mov.b64 {%0,%1}, %2;" : "=f"(lo), "=f"(hi) : "l"(v));
}
static __device__ __forceinline__ ull fma2(ull a, ull b, ull c){
    ull d; asm("fma.rn.f32x2 %0, %1, %2, %3;" : "=l"(d) : "l"(a), "l"(b), "l"(c)); return d;
}
static __device__ __forceinline__ ull mul2(ull a, ull b){
    ull d; asm("mul.rn.f32x2 %0, %1, %2;" : "=l"(d) : "l"(a), "l"(b)); return d;
}
static __device__ __forceinline__ ull dup2(float x){ return pack2(x, x); }

static __device__ __forceinline__ unsigned sa(const void* p){
    return (unsigned)__cvta_generic_to_shared(p);
}
static __device__ __forceinline__ void cp16(unsigned s, const void* g){
    asm volatile("cp.async.ca.shared.global [%0], [%1], 16;" :: "r"(s), "l"(g));
}
static __device__ __forceinline__ void cp8(unsigned s, const void* g){
    asm volatile("cp.async.ca.shared.global [%0], [%1], 8;" :: "r"(s), "l"(g));
}
static __device__ __forceinline__ void cp4(unsigned s, const void* g){
    asm volatile("cp.async.ca.shared.global [%0], [%1], 4;" :: "r"(s), "l"(g));
}

// ---------------------------------------------------------------------------
// Prep: block 0 = W preparation; blocks 1..32 = frames (masked R rows + t).
// ---------------------------------------------------------------------------
__global__ void prep_kernel(const float* __restrict__ X, const void* __restrict__ Cv,
                            const float* __restrict__ Wvec, const float* __restrict__ Wdist){
    if (blockIdx.x == 0){
        int e = threadIdx.x;
        if (e >= 128) return;
        #pragma unroll
        for (int d = 0; d < 3; d++) g_wv[d*HALF_ + e] = TWOPI * Wvec[d*HALF_ + e];
        float b = 0.f;
        #pragma unroll
        for (int m = 0; m < 8; m++) b += Wdist[(m*8+m)*HALF_ + e];
        g_bias[e] = TWOPI * sqrtf(EPSF) * b;
        for (int p = 0; p < NPAIR; p++){
            int m = c_pm[p], n = c_pn[p];
            g_wsym[p*HALF_ + e] = TWOPI * (Wdist[(m*8+n)*HALF_ + e] + Wdist[(n*8+m)*HALF_ + e]);
        }
        return;
    }
    int r = (blockIdx.x - 1)*256 + threadIdx.x;   // 32*256 = 8192
    int4 vc = ((const int4*)Cv)[threadIdx.x & 31];
    int is64C = (__reduce_or_sync(0xffffffffu, vc.y | vc.w) == 0);
    ll cv = is64C ? ((const ll*)Cv)[r] : (ll)((const int*)Cv)[r];
    float mask = (cv > 0) ? 1.f : 0.f;

    const float* x = X + (size_t)r * 12;
    float Nx=x[0], Ny=x[1], Nz=x[2];
    float Ax=x[3], Ay=x[4], Az=x[5];
    float Cx=x[6], Cy=x[7], Cz=x[8];

    float v1x=Nx-Ax, v1y=Ny-Ay, v1z=Nz-Az;
    float n1 = sqrtf(v1x*v1x + v1y*v1y + v1z*v1z) + EPSF;
    float e1x=v1x/n1, e1y=v1y/n1, e1z=v1z/n1;

    float u2x=Cx-Ax, u2y=Cy-Ay, u2z=Cz-Az;
    float n2 = sqrtf(u2x*u2x + u2y*u2y + u2z*u2z) + EPSF;
    u2x/=n2; u2y/=n2; u2z/=n2;

    float dt = u2x*e1x + u2y*e1y + u2z*e1z;
    float w2x = u2x - dt*e1x, w2y = u2y - dt*e1y, w2z = u2z - dt*e1z;
    float n3 = sqrtf(w2x*w2x + w2y*w2y + w2z*w2z) + EPSF;
    float e2x=w2x/n3, e2y=w2y/n3, e2z=w2z/n3;

    float e3x = e1y*e2z - e1z*e2y;
    float e3y = e1z*e2x - e1x*e2z;
    float e3z = e1x*e2y - e1y*e2x;

    float4* g4 = (float4*)g_fr + (size_t)r*4;
    g4[0] = make_float4(mask*e1x, mask*e1y, mask*e1z, 0.f);
    g4[1] = make_float4(mask*e2x, mask*e2y, mask*e2z, 0.f);
    g4[2] = make_float4(mask*e3x, mask*e3y, mask*e3z, 0.f);
    g4[3] = make_float4(mask*Ax,  mask*Ay,  mask*Az,  0.f);
}

// ---------------------------------------------------------------------------
// Persistent main kernel: R13 pipeline skeleton; compute tiling = 128 cols
// (4/lane) x 4 edges per warp -> hot-loop LDS wavefronts cut 84 -> 56/warp.
// ---------------------------------------------------------------------------
__global__ __launch_bounds__(256, 4)
void edge_kernel(const float* __restrict__ X, const void* __restrict__ eidxv,
                 float* __restrict__ out){
    __shared__ __align__(16) float s_wsym[NPAIR*HALF_];  // 14336 B
    __shared__ __align__(16) float s_wv[3*HALF_];        // 1536 B
    __shared__ __align__(16) float s_bias[HALF_];        // 512 B
    __shared__ __align__(16) float s_xj[2][K_*12];       // 3072 B
    __shared__ __align__(16) float s_tj[2][K_*4];        // 1024 B
    __shared__ __align__(16) float s_fri[2][16];         // 128 B
    __shared__ __align__(16) float s_xi[2][12];          // 96 B
    __shared__ __align__(16) ll    s_jb[2][K_];          // 512 B
    __shared__ __align__(16) float s_d[2][K_*NPAIR];     // 7168 B
    __shared__ __align__(16) float s_t[2][K_*4];         // 1024 B

    int tid  = threadIdx.x;
    int w    = tid >> 5, lane = tid & 31;

    int4 ve = ((const int4*)eidxv)[lane];
    int is64 = (__reduce_or_sync(0xffffffffu, ve.y | ve.w) == 0);

    // W staging once per block
    {
        const float4* src = (const float4*)g_wsym;
        float4* dst = (float4*)s_wsym;
        #pragma unroll
        for (int i = tid; i < NPAIR*HALF_/4; i += 256) dst[i] = src[i];
    }
    if (tid < 96)                ((float4*)s_wv)[tid]      = ((const float4*)g_wv)[tid];
    if (tid >= 96 && tid < 128)  ((float4*)s_bias)[tid-96] = ((const float4*)g_bias)[tid-96];

    int kk_x = 0, part_x = 0;
    if (tid < 96){ kk_x = tid/3; part_x = tid - kk_x*3; }

    // synchronous staging of residue rr into slot ss
    auto stage = [&](int rr, int ss){
        int bb = rr & ~(L_-1);
        if (tid < 96){
            ll j = is64 ? ((const ll*)eidxv)[rr*K_ + kk_x]
                        : (ll)((const int*)eidxv)[rr*K_ + kk_x];
            ((float4*)&s_xj[ss][kk_x*12])[part_x] = ((const float4*)X)[(bb+(int)j)*3 + part_x];
        } else if (tid < 128){
            int k = tid - 96;
            ll j = is64 ? ((const ll*)eidxv)[rr*K_ + k]
                        : (ll)((const int*)eidxv)[rr*K_ + k];
            ((float4*)&s_tj[ss][k*4])[0] = ((const float4*)g_fr)[(size_t)(bb+(int)j)*4 + 3];
        } else if (tid < 132){
            ((float4*)s_fri[ss])[tid-128] = ((const float4*)g_fr)[(size_t)rr*4 + (tid-128)];
        } else if (tid < 135){
            ((float4*)s_xi[ss])[tid-132] = ((const float4*)X)[rr*3 + (tid-132)];
        }
    };

    // distance + t_ji for the residue staged in slot ss, writing d-buffer dd
    auto dist = [&](int ss, int dd){
        if (lane < NPAIR){
            int m = c_pm[lane], n = c_pn[lane];
            bool mI = (m < 4), nI = (n < 4);
            float mx=0.f,my=0.f,mz=0.f, nx=0.f,ny=0.f,nz=0.f;
            if (mI){ mx=s_xi[ss][m*3]; my=s_xi[ss][m*3+1]; mz=s_xi[ss][m*3+2]; }
            if (nI){ nx=s_xi[ss][n*3]; ny=s_xi[ss][n*3+1]; nz=s_xi[ss][n*3+2]; }
            #pragma unroll
            for (int e = 0; e < 4; e++){
                int k = w*4 + e;
                const float* xj = &s_xj[ss][k*12];
                float ax = mI ? mx : xj[(m-4)*3+0];
                float ay = mI ? my : xj[(m-4)*3+1];
                float az = mI ? mz : xj[(m-4)*3+2];
                float bx = nI ? nx : xj[(n-4)*3+0];
                float by = nI ? ny : xj[(n-4)*3+1];
                float bz = nI ? nz : xj[(n-4)*3+2];
                float dx=ax-bx, dy=ay-by, dz=az-bz;
                float dd2 = fmaf(dx,dx, fmaf(dy,dy, fmaf(dz,dz, EPSF)));
                s_d[dd][k*NPAIR + lane] = __fsqrt_rn(dd2);
            }
        } else {
            int k = w*4 + (lane - NPAIR);
            float4 f0 = ((const float4*)s_fri[ss])[0];
            float4 f1 = ((const float4*)s_fri[ss])[1];
            float4 f2 = ((const float4*)s_fri[ss])[2];
            float4 f3 = ((const float4*)s_fri[ss])[3];
            float4 tj = ((const float4*)&s_tj[ss][k*4])[0];
            float dx = tj.x - f3.x, dy = tj.y - f3.y, dz = tj.z - f3.z;
            float t0 = fmaf(f0.z,dz, fmaf(f0.y,dy, f0.x*dx));
            float t1 = fmaf(f1.z,dz, fmaf(f1.y,dy, f1.x*dx));
            float t2 = fmaf(f2.z,dz, fmaf(f2.y,dy, f2.x*dx));
            ((float4*)&s_t[dd][k*4])[0] = make_float4(t0, t1, t2, 0.f);
        }
    };

    // --- prologue: stage r0 (slot0) and r0+G (slot1); jb[0] <- idx(r0+2G) ---
    int r0 = blockIdx.x;
    stage(r0, 0);
    if (r0 + GRID_ < BL_) stage(r0 + GRID_, 1);
    if (tid >= 136 && tid < 168 && r0 + 2*GRID_ < BL_){
        int k = tid - 136;
        s_jb[0][k] = is64 ? ((const ll*)eidxv)[(r0+2*GRID_)*K_ + k]
                          : (ll)((const int*)eidxv)[(r0+2*GRID_)*K_ + k];
    }
    __syncthreads();
    dist(0, 0);
    __syncthreads();

    int r = r0, xb = 1, db = 0;
    while (true){
        int rn = r + GRID_;
        int rf = r + 2*GRID_;
        bool hn = rn < BL_;

        // --- prefetch xj(rf) into slot xb^1 (uses jb[xb^1]); jb[xb] <- idx(r+3G) ---
        if (rf < BL_){
            int bb = rf & ~(L_-1);
            if (tid < 96){
                ll j = is64 ? s_jb[xb^1][kk_x] : (ll)(*(const int*)&s_jb[xb^1][kk_x]);
                cp16(sa(&s_xj[xb^1][kk_x*12 + part_x*4]),
                     (const char*)X + ((size_t)(bb+(int)j)*12 + part_x*4)*4);
            } else if (tid < 128){
                int k = tid - 96;
                ll j = is64 ? s_jb[xb^1][k] : (ll)(*(const int*)&s_jb[xb^1][k]);
                cp16(sa(&s_tj[xb^1][k*4]),
                     (const char*)g_fr + ((size_t)(bb+(int)j)*16 + 12)*4);
            } else if (tid < 132){
                cp16(sa(&s_fri[xb^1][(tid-128)*4]),
                     (const char*)g_fr + ((size_t)rf*16 + (tid-128)*4)*4);
            } else if (tid < 135){
                cp16(sa(&s_xi[xb^1][(tid-132)*4]),
                     (const char*)X + ((size_t)rf*12 + (tid-132)*4)*4);
            } else if (tid >= 136 && tid < 168 && r + 3*GRID_ < BL_){
                int k = tid - 136;
                if (is64) cp8(sa(&s_jb[xb][k]),
                              (const char*)eidxv + ((size_t)(r+3*GRID_)*K_ + k)*8);
                else      cp4(sa(&s_jb[xb][k]),
                              (const char*)eidxv + ((size_t)(r+3*GRID_)*K_ + k)*4);
            }
            asm volatile("cp.async.commit_group;" ::: "memory");
        }

        // --- dist(r+G) into s_d[db^1] (hides under other warps' compute) ---
        if (hn) dist(xb, db^1);

        // --- compute(r): 128 cols (4/lane) x 4 edges per warp ---
        {
            int eb  = w * 4;
            int col = lane * 4;

            // hdA[e] = {hd[e][col],hd[e][col+1]}, hdB[e] = {hd[e][col+2],hd[e][col+3]}
            ull hdA[4], hdB[4];
            {
                float4 bq = *(const float4*)&s_bias[col];
                ull bA = pack2(bq.x, bq.y), bB = pack2(bq.z, bq.w);
                #pragma unroll
                for (int e = 0; e < 4; e++){ hdA[e]=bA; hdB[e]=bB; }
            }
            #pragma unroll 1
            for (int pp = 0; pp < NPAIR; pp += 4){
                float4 q0 = *(const float4*)&s_wsym[(pp+0)*HALF_ + col];
                float4 q1 = *(const float4*)&s_wsym[(pp+1)*HALF_ + col];
                float4 q2 = *(const float4*)&s_wsym[(pp+2)*HALF_ + col];
                float4 q3 = *(const float4*)&s_wsym[(pp+3)*HALF_ + col];
                ull W0a=pack2(q0.x,q0.y), W0b=pack2(q0.z,q0.w);
                ull W1a=pack2(q1.x,q1.y), W1b=pack2(q1.z,q1.w);
                ull W2a=pack2(q2.x,q2.y), W2b=pack2(q2.z,q2.w);
                ull W3a=pack2(q3.x,q3.y), W3b=pack2(q3.z,q3.w);
                #pragma unroll
                for (int e = 0; e < 4; e++){
                    float4 dq = *(const float4*)&s_d[db][(eb+e)*NPAIR + pp];  // broadcast
                    ull d0=dup2(dq.x), d1=dup2(dq.y), d2=dup2(dq.z), d3=dup2(dq.w);
                    hdA[e] = fma2(d0, W0a, hdA[e]);  hdB[e] = fma2(d0, W0b, hdB[e]);
                    hdA[e] = fma2(d1, W1a, hdA[e]);  hdB[e] = fma2(d1, W1b, hdB[e]);
                    hdA[e] = fma2(d2, W2a, hdA[e]);  hdB[e] = fma2(d2, W2b, hdB[e]);
                    hdA[e] = fma2(d3, W3a, hdA[e]);  hdB[e] = fma2(d3, W3b, hdB[e]);
                }
            }

            float4 wv0 = *(const float4*)&s_wv[0*HALF_ + col];
            float4 wv1 = *(const float4*)&s_wv[1*HALF_ + col];
            float4 wv2 = *(const float4*)&s_wv[2*HALF_ + col];
            ull v0a=pack2(wv0.x,wv0.y), v0b=pack2(wv0.z,wv0.w);
            ull v1a=pack2(wv1.x,wv1.y), v1b=pack2(wv1.z,wv1.w);
            ull v2a=pack2(wv2.x,wv2.y), v2b=pack2(wv2.z,wv2.w);

            #pragma unroll
            for (int e = 0; e < 4; e++){
                int k = eb + e;
                float4 tq = *(const float4*)&s_t[db][k*4];   // broadcast
                ull t0d = dup2(tq.x), t1d = dup2(tq.y), t2d = dup2(tq.z);
                ull hvA = fma2(t2d, v2a, fma2(t1d, v1a, mul2(t0d, v0a)));
                ull hvB = fma2(t2d, v2b, fma2(t1d, v1b, mul2(t0d, v0b)));

                float a0,a1,a2,a3, b0,b1,b2,b3;
                unpack2(hvA, a0, a1);  unpack2(hvB, a2, a3);
                unpack2(hdA[e], b0, b1);  unpack2(hdB[e], b2, b3);
                float sa0,ca0,sa1,ca1,sa2,ca2,sa3,ca3;
                float sb0,cb0,sb1,cb1,sb2,cb2,sb3,cb3;
                __sincosf(a0,&sa0,&ca0); __sincosf(a1,&sa1,&ca1);
                __sincosf(a2,&sa2,&ca2); __sincosf(a3,&sa3,&ca3);
                __sincosf(b0,&sb0,&cb0); __sincosf(b1,&sb1,&cb1);
                __sincosf(b2,&sb2,&cb2); __sincosf(b3,&sb3,&cb3);
                size_t obase = ((size_t)(r*K_ + k))*256 + col;
                __stcs((float4*)&out[obase],
                       make_float4(ca0+cb0, ca1+cb1, ca2+cb2, ca3+cb3));
                __stcs((float4*)&out[obase + 128],
                       make_float4(sa0+sb0, sa1+sb1, sa2+sb2, sa3+sb3));
            }
        }

        asm volatile("cp.async.wait_group 0;" ::: "memory");
        __syncthreads();
        if (!hn) break;
        r = rn; xb ^= 1; db ^= 1;
    }
}

// ---------------------------------------------------------------------------
extern "C" void kernel_launch(void* const* d_in, const int* in_sizes, int n_in,
                              void* d_out, int out_size){
    const float* X     = (const float*)d_in[0];
    const void*  eidx  = d_in[1];
    const void*  C     = d_in[2];
    const float* Wvec  = (const float*)d_in[3];
    const float* Wdist = (const float*)d_in[4];
    (void)in_sizes; (void)n_in; (void)out_size;

    prep_kernel<<<33, 256>>>(X, C, Wvec, Wdist);
    edge_kernel<<<GRID_, 256>>>(X, eidx, (float*)d_out);
}

// round 16
// speedup vs baseline: 1.7061x; 1.0208x over previous
#include <cuda_runtime.h>
#include <math.h>

#define B_    2
#define L_    4096
#define K_    32
#define HALF_ 128
#define NPAIR 28
#define EPSF  1e-6f
#define TWOPI 6.28318530717958647692f
#define BL_   (B_*L_)
#define GRID_ 608

typedef unsigned long long ull;
typedef long long ll;

__device__ float g_wsym[NPAIR*HALF_];   // 2pi*(W[mn]+W[nm])
__device__ float g_wv[3*HALF_];         // 2pi*W_vec
__device__ float g_bias[HALF_];         // 2pi*sqrt(EPS)*sum_diag W
__device__ float g_fr[BL_*16];          // per res: e1 e2 e3 t (float4 each), masked

__constant__ int c_pm[NPAIR] = {0,0,0,0,0,0,0,1,1,1,1,1,1,2,2,2,2,2,3,3,3,3,4,4,4,5,5,6};
__constant__ int c_pn[NPAIR] = {1,2,3,4,5,6,7,2,3,4,5,6,7,3,4,5,6,7,4,5,6,7,5,6,7,6,7,7};

static __device__ __forceinline__ ull pack2(float lo, float hi){
    ull r; asm("mov.b64 %0, {%1,%2};" : "=l"(r) : "f"(lo), "f"(hi)); return r;
}
static __device__ __forceinline__ void unpack2(ull v, float& lo, float& hi){
    asm("mov.b64 {%0,%1}, %2;" : "=f"(lo), "=f"(hi) : "l"(v));
}
static __device__ __forceinline__ ull fma2(ull a, ull b, ull c){
    ull d; asm("fma.rn.f32x2 %0, %1, %2, %3;" : "=l"(d) : "l"(a), "l"(b), "l"(c)); return d;
}
static __device__ __forceinline__ ull mul2(ull a, ull b){
    ull d; asm("mul.rn.f32x2 %0, %1, %2;" : "=l"(d) : "l"(a), "l"(b)); return d;
}
static __device__ __forceinline__ ull dup2(float x){ return pack2(x, x); }

static __device__ __forceinline__ unsigned sa(const void* p){
    return (unsigned)__cvta_generic_to_shared(p);
}
static __device__ __forceinline__ void cp16(unsigned s, const void* g){
    asm volatile("cp.async.ca.shared.global [%0], [%1], 16;" :: "r"(s), "l"(g));
}
static __device__ __forceinline__ void cp8(unsigned s, const void* g){
    asm volatile("cp.async.ca.shared.global [%0], [%1], 8;" :: "r"(s), "l"(g));
}
static __device__ __forceinline__ void cp4(unsigned s, const void* g){
    asm volatile("cp.async.ca.shared.global [%0], [%1], 4;" :: "r"(s), "l"(g));
}

// ---------------------------------------------------------------------------
// Prep: block 0 = W preparation; blocks 1..32 = frames (masked R rows + t).
// ---------------------------------------------------------------------------
__global__ void prep_kernel(const float* __restrict__ X, const void* __restrict__ Cv,
                            const float* __restrict__ Wvec, const float* __restrict__ Wdist){
    if (blockIdx.x == 0){
        int e = threadIdx.x;
        if (e >= 128) return;
        #pragma unroll
        for (int d = 0; d < 3; d++) g_wv[d*HALF_ + e] = TWOPI * Wvec[d*HALF_ + e];
        float b = 0.f;
        #pragma unroll
        for (int m = 0; m < 8; m++) b += Wdist[(m*8+m)*HALF_ + e];
        g_bias[e] = TWOPI * sqrtf(EPSF) * b;
        for (int p = 0; p < NPAIR; p++){
            int m = c_pm[p], n = c_pn[p];
            g_wsym[p*HALF_ + e] = TWOPI * (Wdist[(m*8+n)*HALF_ + e] + Wdist[(n*8+m)*HALF_ + e]);
        }
        return;
    }
    int r = (blockIdx.x - 1)*256 + threadIdx.x;   // 32*256 = 8192
    int4 vc = ((const int4*)Cv)[threadIdx.x & 31];
    int is64C = (__reduce_or_sync(0xffffffffu, vc.y | vc.w) == 0);
    ll cv = is64C ? ((const ll*)Cv)[r] : (ll)((const int*)Cv)[r];
    float mask = (cv > 0) ? 1.f : 0.f;

    const float* x = X + (size_t)r * 12;
    float Nx=x[0], Ny=x[1], Nz=x[2];
    float Ax=x[3], Ay=x[4], Az=x[5];
    float Cx=x[6], Cy=x[7], Cz=x[8];

    float v1x=Nx-Ax, v1y=Ny-Ay, v1z=Nz-Az;
    float n1 = sqrtf(v1x*v1x + v1y*v1y + v1z*v1z) + EPSF;
    float e1x=v1x/n1, e1y=v1y/n1, e1z=v1z/n1;

    float u2x=Cx-Ax, u2y=Cy-Ay, u2z=Cz-Az;
    float n2 = sqrtf(u2x*u2x + u2y*u2y + u2z*u2z) + EPSF;
    u2x/=n2; u2y/=n2; u2z/=n2;

    float dt = u2x*e1x + u2y*e1y + u2z*e1z;
    float w2x = u2x - dt*e1x, w2y = u2y - dt*e1y, w2z = u2z - dt*e1z;
    float n3 = sqrtf(w2x*w2x + w2y*w2y + w2z*w2z) + EPSF;
    float e2x=w2x/n3, e2y=w2y/n3, e2z=w2z/n3;

    float e3x = e1y*e2z - e1z*e2y;
    float e3y = e1z*e2x - e1x*e2z;
    float e3z = e1x*e2y - e1y*e2x;

    float4* g4 = (float4*)g_fr + (size_t)r*4;
    g4[0] = make_float4(mask*e1x, mask*e1y, mask*e1z, 0.f);
    g4[1] = make_float4(mask*e2x, mask*e2y, mask*e2z, 0.f);
    g4[2] = make_float4(mask*e3x, mask*e3y, mask*e3z, 0.f);
    g4[3] = make_float4(mask*Ax,  mask*Ay,  mask*Az,  0.f);
}

// ---------------------------------------------------------------------------
// Persistent main kernel: R14 structure; residue-invariant wv/bias hoisted to
// registers outside the persistent loop; hot loop unrolled 2x.
// ---------------------------------------------------------------------------
__global__ __launch_bounds__(256, 4)
void edge_kernel(const float* __restrict__ X, const void* __restrict__ eidxv,
                 float* __restrict__ out){
    __shared__ __align__(16) float s_wsym[NPAIR*HALF_];  // 14336 B
    __shared__ __align__(16) float s_wv[3*HALF_];        // 1536 B
    __shared__ __align__(16) float s_bias[HALF_];        // 512 B
    __shared__ __align__(16) float s_xj[2][K_*12];       // 3072 B
    __shared__ __align__(16) float s_tj[2][K_*4];        // 1024 B
    __shared__ __align__(16) float s_fri[2][16];         // 128 B
    __shared__ __align__(16) float s_xi[2][12];          // 96 B
    __shared__ __align__(16) ll    s_jb[2][K_];          // 512 B
    __shared__ __align__(16) float s_d[2][K_*NPAIR];     // 7168 B
    __shared__ __align__(16) float s_t[2][K_*4];         // 1024 B

    int tid  = threadIdx.x;
    int w    = tid >> 5, lane = tid & 31;

    int4 ve = ((const int4*)eidxv)[lane];
    int is64 = (__reduce_or_sync(0xffffffffu, ve.y | ve.w) == 0);

    // W staging once per block
    {
        const float4* src = (const float4*)g_wsym;
        float4* dst = (float4*)s_wsym;
        #pragma unroll
        for (int i = tid; i < NPAIR*HALF_/4; i += 256) dst[i] = src[i];
    }
    if (tid < 96)                ((float4*)s_wv)[tid]      = ((const float4*)g_wv)[tid];
    if (tid >= 96 && tid < 128)  ((float4*)s_bias)[tid-96] = ((const float4*)g_bias)[tid-96];

    int kk_x = 0, part_x = 0;
    if (tid < 96){ kk_x = tid/3; part_x = tid - kk_x*3; }

    // synchronous staging of residue rr into slot ss
    auto stage = [&](int rr, int ss){
        int bb = rr & ~(L_-1);
        if (tid < 96){
            ll j = is64 ? ((const ll*)eidxv)[rr*K_ + kk_x]
                        : (ll)((const int*)eidxv)[rr*K_ + kk_x];
            ((float4*)&s_xj[ss][kk_x*12])[part_x] = ((const float4*)X)[(bb+(int)j)*3 + part_x];
        } else if (tid < 128){
            int k = tid - 96;
            ll j = is64 ? ((const ll*)eidxv)[rr*K_ + k]
                        : (ll)((const int*)eidxv)[rr*K_ + k];
            ((float4*)&s_tj[ss][k*4])[0] = ((const float4*)g_fr)[(size_t)(bb+(int)j)*4 + 3];
        } else if (tid < 132){
            ((float4*)s_fri[ss])[tid-128] = ((const float4*)g_fr)[(size_t)rr*4 + (tid-128)];
        } else if (tid < 135){
            ((float4*)s_xi[ss])[tid-132] = ((const float4*)X)[rr*3 + (tid-132)];
        }
    };

    // distance + t_ji for the residue staged in slot ss, writing d-buffer dd
    auto dist = [&](int ss, int dd){
        if (lane < NPAIR){
            int m = c_pm[lane], n = c_pn[lane];
            bool mI = (m < 4), nI = (n < 4);
            float mx=0.f,my=0.f,mz=0.f, nx=0.f,ny=0.f,nz=0.f;
            if (mI){ mx=s_xi[ss][m*3]; my=s_xi[ss][m*3+1]; mz=s_xi[ss][m*3+2]; }
            if (nI){ nx=s_xi[ss][n*3]; ny=s_xi[ss][n*3+1]; nz=s_xi[ss][n*3+2]; }
            #pragma unroll
            for (int e = 0; e < 4; e++){
                int k = w*4 + e;
                const float* xj = &s_xj[ss][k*12];
                float ax = mI ? mx : xj[(m-4)*3+0];
                float ay = mI ? my : xj[(m-4)*3+1];
                float az = mI ? mz : xj[(m-4)*3+2];
                float bx = nI ? nx : xj[(n-4)*3+0];
                float by = nI ? ny : xj[(n-4)*3+1];
                float bz = nI ? nz : xj[(n-4)*3+2];
                float dx=ax-bx, dy=ay-by, dz=az-bz;
                float dd2 = fmaf(dx,dx, fmaf(dy,dy, fmaf(dz,dz, EPSF)));
                s_d[dd][k*NPAIR + lane] = __fsqrt_rn(dd2);
            }
        } else {
            int k = w*4 + (lane - NPAIR);
            float4 f0 = ((const float4*)s_fri[ss])[0];
            float4 f1 = ((const float4*)s_fri[ss])[1];
            float4 f2 = ((const float4*)s_fri[ss])[2];
            float4 f3 = ((const float4*)s_fri[ss])[3];
            float4 tj = ((const float4*)&s_tj[ss][k*4])[0];
            float dx = tj.x - f3.x, dy = tj.y - f3.y, dz = tj.z - f3.z;
            float t0 = fmaf(f0.z,dz, fmaf(f0.y,dy, f0.x*dx));
            float t1 = fmaf(f1.z,dz, fmaf(f1.y,dy, f1.x*dx));
            float t2 = fmaf(f2.z,dz, fmaf(f2.y,dy, f2.x*dx));
            ((float4*)&s_t[dd][k*4])[0] = make_float4(t0, t1, t2, 0.f);
        }
    };

    // --- prologue: stage r0 (slot0) and r0+G (slot1); jb[0] <- idx(r0+2G) ---
    int r0 = blockIdx.x;
    stage(r0, 0);
    if (r0 + GRID_ < BL_) stage(r0 + GRID_, 1);
    if (tid >= 136 && tid < 168 && r0 + 2*GRID_ < BL_){
        int k = tid - 136;
        s_jb[0][k] = is64 ? ((const ll*)eidxv)[(r0+2*GRID_)*K_ + k]
                          : (ll)((const int*)eidxv)[(r0+2*GRID_)*K_ + k];
    }
    __syncthreads();
    dist(0, 0);
    __syncthreads();

    // --- residue-invariant per-lane constants hoisted out of the loop ---
    int eb  = w * 4;
    int col = lane * 4;
    ull bA, bB, v0a, v0b, v1a, v1b, v2a, v2b;
    {
        float4 bq  = *(const float4*)&s_bias[col];
        float4 wv0 = *(const float4*)&s_wv[0*HALF_ + col];
        float4 wv1 = *(const float4*)&s_wv[1*HALF_ + col];
        float4 wv2 = *(const float4*)&s_wv[2*HALF_ + col];
        bA  = pack2(bq.x, bq.y);   bB  = pack2(bq.z, bq.w);
        v0a = pack2(wv0.x,wv0.y);  v0b = pack2(wv0.z,wv0.w);
        v1a = pack2(wv1.x,wv1.y);  v1b = pack2(wv1.z,wv1.w);
        v2a = pack2(wv2.x,wv2.y);  v2b = pack2(wv2.z,wv2.w);
    }

    int r = r0, xb = 1, db = 0;
    while (true){
        int rn = r + GRID_;
        int rf = r + 2*GRID_;
        bool hn = rn < BL_;

        // --- prefetch xj(rf) into slot xb^1 (uses jb[xb^1]); jb[xb] <- idx(r+3G) ---
        if (rf < BL_){
            int bb = rf & ~(L_-1);
            if (tid < 96){
                ll j = is64 ? s_jb[xb^1][kk_x] : (ll)(*(const int*)&s_jb[xb^1][kk_x]);
                cp16(sa(&s_xj[xb^1][kk_x*12 + part_x*4]),
                     (const char*)X + ((size_t)(bb+(int)j)*12 + part_x*4)*4);
            } else if (tid < 128){
                int k = tid - 96;
                ll j = is64 ? s_jb[xb^1][k] : (ll)(*(const int*)&s_jb[xb^1][k]);
                cp16(sa(&s_tj[xb^1][k*4]),
                     (const char*)g_fr + ((size_t)(bb+(int)j)*16 + 12)*4);
            } else if (tid < 132){
                cp16(sa(&s_fri[xb^1][(tid-128)*4]),
                     (const char*)g_fr + ((size_t)rf*16 + (tid-128)*4)*4);
            } else if (tid < 135){
                cp16(sa(&s_xi[xb^1][(tid-132)*4]),
                     (const char*)X + ((size_t)rf*12 + (tid-132)*4)*4);
            } else if (tid >= 136 && tid < 168 && r + 3*GRID_ < BL_){
                int k = tid - 136;
                if (is64) cp8(sa(&s_jb[xb][k]),
                              (const char*)eidxv + ((size_t)(r+3*GRID_)*K_ + k)*8);
                else      cp4(sa(&s_jb[xb][k]),
                              (const char*)eidxv + ((size_t)(r+3*GRID_)*K_ + k)*4);
            }
            asm volatile("cp.async.commit_group;" ::: "memory");
        }

        // --- dist(r+G) into s_d[db^1] (hides under other warps' compute) ---
        if (hn) dist(xb, db^1);

        // --- compute(r): 128 cols (4/lane) x 4 edges per warp ---
        {
            ull hdA[4], hdB[4];
            #pragma unroll
            for (int e = 0; e < 4; e++){ hdA[e]=bA; hdB[e]=bB; }

            #pragma unroll 2
            for (int pp = 0; pp < NPAIR; pp += 4){
                float4 q0 = *(const float4*)&s_wsym[(pp+0)*HALF_ + col];
                float4 q1 = *(const float4*)&s_wsym[(pp+1)*HALF_ + col];
                float4 q2 = *(const float4*)&s_wsym[(pp+2)*HALF_ + col];
                float4 q3 = *(const float4*)&s_wsym[(pp+3)*HALF_ + col];
                ull W0a=pack2(q0.x,q0.y), W0b=pack2(q0.z,q0.w);
                ull W1a=pack2(q1.x,q1.y), W1b=pack2(q1.z,q1.w);
                ull W2a=pack2(q2.x,q2.y), W2b=pack2(q2.z,q2.w);
                ull W3a=pack2(q3.x,q3.y), W3b=pack2(q3.z,q3.w);
                #pragma unroll
                for (int e = 0; e < 4; e++){
                    float4 dq = *(const float4*)&s_d[db][(eb+e)*NPAIR + pp];  // broadcast
                    ull d0=dup2(dq.x), d1=dup2(dq.y), d2=dup2(dq.z), d3=dup2(dq.w);
                    hdA[e] = fma2(d0, W0a, hdA[e]);  hdB[e] = fma2(d0, W0b, hdB[e]);
                    hdA[e] = fma2(d1, W1a, hdA[e]);  hdB[e] = fma2(d1, W1b, hdB[e]);
                    hdA[e] = fma2(d2, W2a, hdA[e]);  hdB[e] = fma2(d2, W2b, hdB[e]);
                    hdA[e] = fma2(d3, W3a, hdA[e]);  hdB[e] = fma2(d3, W3b, hdB[e]);
                }
            }

            #pragma unroll
            for (int e = 0; e < 4; e++){
                int k = eb + e;
                float4 tq = *(const float4*)&s_t[db][k*4];   // broadcast
                ull t0d = dup2(tq.x), t1d = dup2(tq.y), t2d = dup2(tq.z);
                ull hvA = fma2(t2d, v2a, fma2(t1d, v1a, mul2(t0d, v0a)));
                ull hvB = fma2(t2d, v2b, fma2(t1d, v1b, mul2(t0d, v0b)));

                float a0,a1,a2,a3, b0,b1,b2,b3;
                unpack2(hvA, a0, a1);  unpack2(hvB, a2, a3);
                unpack2(hdA[e], b0, b1);  unpack2(hdB[e], b2, b3);
                float sa0,ca0,sa1,ca1,sa2,ca2,sa3,ca3;
                float sb0,cb0,sb1,cb1,sb2,cb2,sb3,cb3;
                __sincosf(a0,&sa0,&ca0); __sincosf(a1,&sa1,&ca1);
                __sincosf(a2,&sa2,&ca2); __sincosf(a3,&sa3,&ca3);
                __sincosf(b0,&sb0,&cb0); __sincosf(b1,&sb1,&cb1);
                __sincosf(b2,&sb2,&cb2); __sincosf(b3,&sb3,&cb3);
                size_t obase = ((size_t)(r*K_ + k))*256 + col;
                __stcs((float4*)&out[obase],
                       make_float4(ca0+cb0, ca1+cb1, ca2+cb2, ca3+cb3));
                __stcs((float4*)&out[obase + 128],
                       make_float4(sa0+sb0, sa1+sb1, sa2+sb2, sa3+sb3));
            }
        }

        asm volatile("cp.async.wait_group 0;" ::: "memory");
        __syncthreads();
        if (!hn) break;
        r = rn; xb ^= 1; db ^= 1;
    }
}

// ---------------------------------------------------------------------------
extern "C" void kernel_launch(void* const* d_in, const int* in_sizes, int n_in,
                              void* d_out, int out_size){
    const float* X     = (const float*)d_in[0];
    const void*  eidx  = d_in[1];
    const void*  C     = d_in[2];
    const float* Wvec  = (const float*)d_in[3];
    const float* Wdist = (const float*)d_in[4];
    (void)in_sizes; (void)n_in; (void)out_size;

    prep_kernel<<<33, 256>>>(X, C, Wvec, Wdist);
    edge_kernel<<<GRID_, 256>>>(X, eidx, (float*)d_out);
}